// round 15
// baseline (speedup 1.0000x reference)
#include <cuda_runtime.h>
#include <cuda_bf16.h>
#include <cstddef>
#include <cstdint>

#define S_IMG  2048
#define S_TXT  512
#define S_TOT  2560
#define DMODEL 1536
#define NH     24
#define DH     64

typedef unsigned long long ull;

// ---------------- scratch (no allocations allowed) ----------------
#define WSZ (DMODEL * DMODEL)
#define QKVN (NH * S_TOT * DH)
__device__ float g_Q[QKVN];                                   // [h][s][d] fp32 (pre-norm)
__device__ float g_K[QKVN];
__device__ float g_V[QKVN];
__device__ __align__(16) __nv_bfloat16 g_Whi[8 * WSZ];
__device__ __align__(16) __nv_bfloat16 g_Wlo[8 * WSZ];
__device__ __align__(16) __nv_bfloat16 g_Xhi[S_TOT * DMODEL];
__device__ __align__(16) __nv_bfloat16 g_Xlo[S_TOT * DMODEL];
__device__ __align__(16) __nv_bfloat16 g_Ohi[S_TOT * DMODEL]; // [s][h*64+d]
__device__ __align__(16) __nv_bfloat16 g_Olo[S_TOT * DMODEL];
__device__ __align__(16) __nv_bfloat16 g_Qhi[QKVN], g_Qlo[QKVN];   // [h][s][d], x0.125
__device__ __align__(16) __nv_bfloat16 g_Khi[QKVN], g_Klo[QKVN];   // [h][s][d]
__device__ __align__(16) __nv_bfloat16 g_Vthi[QKVN], g_Vtlo[QKVN]; // [h][d][s]

// ---------------- helpers ----------------
__device__ __forceinline__ unsigned smem_u32(const void* p) {
    unsigned a;
    asm("{ .reg .u64 t; cvta.to.shared.u64 t, %1; cvt.u32.u64 %0, t; }" : "=r"(a) : "l"(p));
    return a;
}
__device__ __forceinline__ void cp16(unsigned dst, const void* src) {
    asm volatile("cp.async.cg.shared.global [%0], [%1], 16;" :: "r"(dst), "l"(src) : "memory");
}
__device__ __forceinline__ void ldsm4(uint32_t* r, unsigned a) {
    asm volatile("ldmatrix.sync.aligned.m8n8.x4.shared.b16 {%0,%1,%2,%3}, [%4];"
        : "=r"(r[0]), "=r"(r[1]), "=r"(r[2]), "=r"(r[3]) : "r"(a));
}
// NOT volatile: register-only op, lets ptxas schedule around HMMA latency
__device__ __forceinline__ void mma16816(float* c, const uint32_t* a, uint32_t b0, uint32_t b1) {
    asm("mma.sync.aligned.m16n8k16.row.col.f32.bf16.bf16.f32 "
        "{%0,%1,%2,%3}, {%4,%5,%6,%7}, {%8,%9}, {%0,%1,%2,%3};"
        : "+f"(c[0]), "+f"(c[1]), "+f"(c[2]), "+f"(c[3])
        : "r"(a[0]), "r"(a[1]), "r"(a[2]), "r"(a[3]), "r"(b0), "r"(b1));
}
__device__ __forceinline__ uint32_t bfpair(float lo, float hi) {   // reg.lo=lo, reg.hi=hi
    uint32_t r; asm("cvt.rn.bf16x2.f32 %0, %1, %2;" : "=r"(r) : "f"(hi), "f"(lo)); return r;
}
__device__ __forceinline__ float bfround(float x) {
    return __bfloat162float(__float2bfloat16(x));
}

// ---------------- splits ----------------
__global__ void split4(const float* __restrict__ src, __nv_bfloat16* __restrict__ hi,
                       __nv_bfloat16* __restrict__ lo, int n4)
{
    int i = blockIdx.x * 256 + threadIdx.x;
    if (i < n4) {
        float4 v = ((const float4*)src)[i];
        __nv_bfloat162 h0{__float2bfloat16(v.x), __float2bfloat16(v.y)};
        __nv_bfloat162 h1{__float2bfloat16(v.z), __float2bfloat16(v.w)};
        ((__nv_bfloat162*)hi)[2 * i]     = h0;
        ((__nv_bfloat162*)hi)[2 * i + 1] = h1;
        __nv_bfloat162 l0{__float2bfloat16(v.x - __bfloat162float(h0.x)),
                          __float2bfloat16(v.y - __bfloat162float(h0.y))};
        __nv_bfloat162 l1{__float2bfloat16(v.z - __bfloat162float(h1.x)),
                          __float2bfloat16(v.w - __bfloat162float(h1.y))};
        ((__nv_bfloat162*)lo)[2 * i]     = l0;
        ((__nv_bfloat162*)lo)[2 * i + 1] = l1;
    }
}

__global__ void splitW(const float* w0, const float* w1, const float* w2, const float* w3,
                       const float* w4, const float* w5, const float* w6, const float* w7,
                       __nv_bfloat16* __restrict__ hi, __nv_bfloat16* __restrict__ lo)
{
    const float* ws[8] = {w0, w1, w2, w3, w4, w5, w6, w7};
    const int wsel = blockIdx.y;
    const float* src = ws[wsel];
    int i = blockIdx.x * 256 + threadIdx.x;
    if (i < WSZ / 4) {
        float4 v = ((const float4*)src)[i];
        const size_t o2 = (size_t)wsel * (WSZ / 2) + 2 * i;
        __nv_bfloat162 h0{__float2bfloat16(v.x), __float2bfloat16(v.y)};
        __nv_bfloat162 h1{__float2bfloat16(v.z), __float2bfloat16(v.w)};
        ((__nv_bfloat162*)hi)[o2]     = h0;
        ((__nv_bfloat162*)hi)[o2 + 1] = h1;
        __nv_bfloat162 l0{__float2bfloat16(v.x - __bfloat162float(h0.x)),
                          __float2bfloat16(v.y - __bfloat162float(h0.y))};
        __nv_bfloat162 l1{__float2bfloat16(v.z - __bfloat162float(h1.x)),
                          __float2bfloat16(v.w - __bfloat162float(h1.y))};
        ((__nv_bfloat162*)lo)[o2]     = l0;
        ((__nv_bfloat162*)lo)[o2 + 1] = l1;
    }
}

// V transpose+split: [h][s][d] fp32 -> [h][d][s] bf16 hi/lo
__global__ void vtsplit(const float* __restrict__ V,
                        __nv_bfloat16* __restrict__ Vth, __nv_bfloat16* __restrict__ Vtl)
{
    __shared__ float t[32][33];
    const int h = blockIdx.z;
    const int s0 = blockIdx.x * 32, d0 = blockIdx.y * 32;
    const int tx = threadIdx.x, ty = threadIdx.y;
    const float* Vh_ = V + (size_t)h * S_TOT * DH;
    #pragma unroll
    for (int j = 0; j < 4; j++)
        t[ty + 8 * j][tx] = Vh_[(size_t)(s0 + ty + 8 * j) * DH + d0 + tx];
    __syncthreads();
    __nv_bfloat16* oh = Vth + (size_t)h * DH * S_TOT;
    __nv_bfloat16* ol = Vtl + (size_t)h * DH * S_TOT;
    #pragma unroll
    for (int j = 0; j < 4; j++) {
        const float v = t[tx][ty + 8 * j];
        const __nv_bfloat16 hh = __float2bfloat16(v);
        const size_t o = (size_t)(d0 + ty + 8 * j) * S_TOT + s0 + tx;
        oh[o] = hh;
        ol[o] = __float2bfloat16(v - __bfloat162float(hh));
    }
}

// ---------------- RMS-norm + gain + RoPE, fused bf16 hi/lo split ----------------
__global__ __launch_bounds__(128)
void rmsrope_split(const float* __restrict__ buf, const float* __restrict__ g_txt,
                   const float* __restrict__ g_img, const float* __restrict__ rcos,
                   const float* __restrict__ rsin, float scale,
                   __nv_bfloat16* __restrict__ hi, __nv_bfloat16* __restrict__ lo)
{
    const int warp = threadIdx.x >> 5;
    const int lane = threadIdx.x & 31;
    const int row  = blockIdx.x * 4 + warp;
    const int s    = row % S_TOT;

    float2 x = *(const float2*)&buf[(size_t)row * 64 + lane * 2];
    float ss = x.x * x.x + x.y * x.y;
    #pragma unroll
    for (int off = 16; off > 0; off >>= 1)
        ss += __shfl_xor_sync(0xffffffffu, ss, off);
    const float r = rsqrtf(ss * (1.0f / 64.0f) + 1e-6f);

    const float* g = (s < S_TXT) ? g_txt : g_img;
    const float y0 = x.x * r * g[lane * 2];
    const float y1 = x.y * r * g[lane * 2 + 1];
    const float c  = rcos[s * 64 + lane * 2];
    const float sn = rsin[s * 64 + lane * 2];
    const float o0 = (y0 * c - y1 * sn) * scale;
    const float o1 = (y1 * c + y0 * sn) * scale;
    const __nv_bfloat16 h0 = __float2bfloat16(o0);
    const __nv_bfloat16 h1 = __float2bfloat16(o1);
    ((__nv_bfloat162*)hi)[(size_t)row * 32 + lane] = __nv_bfloat162{h0, h1};
    ((__nv_bfloat162*)lo)[(size_t)row * 32 + lane] = __nv_bfloat162{
        __float2bfloat16(o0 - __bfloat162float(h0)),
        __float2bfloat16(o1 - __bfloat162float(h1))};
}

// ================= warp-MMA bf16 GEMM (ldmatrix + term-major MMA order) =================
#define GBK      32
#define GSTRIDE  40
#define GBUF     (128 * GSTRIDE * 2)
#define GSTAGE   (4 * GBUF)
#define GEMM_SMEM (2 * GSTAGE)

__device__ void mma_core(const __nv_bfloat16* __restrict__ Ah, const __nv_bfloat16* __restrict__ Al,
                         const __nv_bfloat16* __restrict__ Wh, const __nv_bfloat16* __restrict__ Wl,
                         char* smem, float acc[2][8][4])
{
    const int tid  = threadIdx.x;
    const int lane = tid & 31;
    const int wid  = tid >> 5;
    const int Rm   = (wid & 3) * 32;
    const int Cn   = (wid >> 2) * 64;
    const int lr   = lane & 7, sel = lane >> 3;
    const int aOff = ((sel & 1) * 8 + lr) * GSTRIDE + (sel & 2) * 4;
    const int bOff = ((sel >> 1) * 8 + lr) * GSTRIDE + (sel & 1) * 8;

    const unsigned sb = smem_u32(smem);
    const __nv_bfloat16* gsrc[4] = {Ah, Al, Wh, Wl};

    auto issue = [&](int c, int stage) {
        #pragma unroll
        for (int t4 = 0; t4 < 4; t4++) {
            const __nv_bfloat16* s = gsrc[t4] + c * GBK;
            const unsigned dbase = sb + stage * GSTAGE + t4 * GBUF;
            #pragma unroll
            for (int i = 0; i < 2; i++) {
                const int idx = tid + i * 256;
                const int row = idx >> 2, cg = idx & 3;
                cp16(dbase + (row * GSTRIDE + cg * 8) * 2,
                     s + (size_t)row * DMODEL + cg * 8);
            }
        }
        asm volatile("cp.async.commit_group;" ::: "memory");
    };

    #pragma unroll
    for (int mi = 0; mi < 2; mi++)
        #pragma unroll
        for (int ni = 0; ni < 8; ni++)
            #pragma unroll
            for (int j = 0; j < 4; j++) acc[mi][ni][j] = 0.0f;

    issue(0, 0);

    for (int c = 0; c < DMODEL / GBK; c++) {
        asm volatile("cp.async.wait_group 0;" ::: "memory");
        __syncthreads();
        if (c + 1 < DMODEL / GBK) issue(c + 1, (c + 1) & 1);

        const unsigned uSt = sb + (c & 1) * GSTAGE;

        #pragma unroll
        for (int k0 = 0; k0 < GBK; k0 += 16) {
            uint32_t ah[2][4], al[2][4];
            #pragma unroll
            for (int mi = 0; mi < 2; mi++) {
                const unsigned ao = uSt + 2u * ((Rm + mi * 16) * GSTRIDE + k0 + aOff);
                ldsm4(ah[mi], ao);
                ldsm4(al[mi], ao + GBUF);
            }
            // process n-tiles in pairs; term-major MMA order (dep distance 8)
            #pragma unroll
            for (int npp = 0; npp < 4; npp += 2) {
                uint32_t bh[2][4], bl[2][4];
                #pragma unroll
                for (int q = 0; q < 2; q++) {
                    const unsigned bo = uSt + 2 * GBUF +
                        2u * ((Cn + (npp + q) * 16) * GSTRIDE + k0 + bOff);
                    ldsm4(bh[q], bo);
                    ldsm4(bl[q], bo + GBUF);
                }
                // term hh
                #pragma unroll
                for (int q = 0; q < 2; q++)
                    #pragma unroll
                    for (int mi = 0; mi < 2; mi++) {
                        mma16816(acc[mi][2 * (npp + q)],     ah[mi], bh[q][0], bh[q][1]);
                        mma16816(acc[mi][2 * (npp + q) + 1], ah[mi], bh[q][2], bh[q][3]);
                    }
                // term hl
                #pragma unroll
                for (int q = 0; q < 2; q++)
                    #pragma unroll
                    for (int mi = 0; mi < 2; mi++) {
                        mma16816(acc[mi][2 * (npp + q)],     ah[mi], bl[q][0], bl[q][1]);
                        mma16816(acc[mi][2 * (npp + q) + 1], ah[mi], bl[q][2], bl[q][3]);
                    }
                // term lh
                #pragma unroll
                for (int q = 0; q < 2; q++)
                    #pragma unroll
                    for (int mi = 0; mi < 2; mi++) {
                        mma16816(acc[mi][2 * (npp + q)],     al[mi], bh[q][0], bh[q][1]);
                        mma16816(acc[mi][2 * (npp + q) + 1], al[mi], bh[q][2], bh[q][3]);
                    }
            }
        }
    }
}

__global__ __launch_bounds__(256, 2)
void qkv_mma(const __nv_bfloat16* __restrict__ Xhi, const __nv_bfloat16* __restrict__ Xlo,
             const __nv_bfloat16* __restrict__ Whi8, const __nv_bfloat16* __restrict__ Wlo8,
             const float* __restrict__ bq, const float* __restrict__ bk, const float* __restrict__ bv,
             const float* __restrict__ baq, const float* __restrict__ bak, const float* __restrict__ bav,
             float* __restrict__ Qp, float* __restrict__ Kp, float* __restrict__ Vp)
{
    extern __shared__ __align__(16) char smem[];
    const int bx = blockIdx.x, mt = blockIdx.y;
    const int proj = bx / 12;
    const int n0b  = (bx % 12) * 128;
    const bool txt = (mt < 4);
    const int widx = (txt ? 3 : 0) + proj;

    const __nv_bfloat16* Ah = Xhi + (size_t)mt * 128 * DMODEL;
    const __nv_bfloat16* Al = Xlo + (size_t)mt * 128 * DMODEL;
    const __nv_bfloat16* Wh = Whi8 + (size_t)widx * WSZ + (size_t)n0b * DMODEL;
    const __nv_bfloat16* Wl = Wlo8 + (size_t)widx * WSZ + (size_t)n0b * DMODEL;
    const float* bias = txt ? (proj == 0 ? baq : proj == 1 ? bak : bav)
                            : (proj == 0 ? bq  : proj == 1 ? bk  : bv);
    float* out = proj == 0 ? Qp : proj == 1 ? Kp : Vp;

    float acc[2][8][4];
    mma_core(Ah, Al, Wh, Wl, smem, acc);

    const int lane = threadIdx.x & 31, wid = threadIdx.x >> 5;
    const int Rm = (wid & 3) * 32, Cn = (wid >> 2) * 64;
    const int gp = lane >> 2, qd = lane & 3;

    #pragma unroll
    for (int ni = 0; ni < 8; ni++) {
        const int n0 = n0b + Cn + ni * 8;
        const int h = n0 >> 6, d0 = (n0 & 63) + qd * 2;
        const float2 bb = *(const float2*)&bias[n0 + qd * 2];
        #pragma unroll
        for (int mi = 0; mi < 2; mi++) {
            const int s = mt * 128 + Rm + mi * 16 + gp;
            float* p0 = out + (((size_t)h * S_TOT + s) << 6) + d0;
            float* p1 = out + (((size_t)h * S_TOT + s + 8) << 6) + d0;
            *(float2*)p0 = make_float2(acc[mi][ni][0] + bb.x, acc[mi][ni][1] + bb.y);
            *(float2*)p1 = make_float2(acc[mi][ni][2] + bb.x, acc[mi][ni][3] + bb.y);
        }
    }
}

__global__ __launch_bounds__(256, 2)
void out_mma(const __nv_bfloat16* __restrict__ Ohi, const __nv_bfloat16* __restrict__ Olo,
             const __nv_bfloat16* __restrict__ Whi8, const __nv_bfloat16* __restrict__ Wlo8,
             const float* __restrict__ bo, const float* __restrict__ bao,
             float* __restrict__ out)
{
    extern __shared__ __align__(16) char smem[];
    const int nt = blockIdx.x, mt = blockIdx.y;
    const int r0 = mt * 128;
    const bool img = (r0 < S_IMG);
    const size_t arow = img ? (size_t)(S_TXT + r0) : (size_t)(r0 - S_IMG);
    const int widx = img ? 6 : 7;

    const __nv_bfloat16* Ah = Ohi + arow * DMODEL;
    const __nv_bfloat16* Al = Olo + arow * DMODEL;
    const __nv_bfloat16* Wh = Whi8 + (size_t)widx * WSZ + (size_t)nt * 128 * DMODEL;
    const __nv_bfloat16* Wl = Wlo8 + (size_t)widx * WSZ + (size_t)nt * 128 * DMODEL;
    const float* bias = img ? bo : bao;

    float acc[2][8][4];
    mma_core(Ah, Al, Wh, Wl, smem, acc);

    const int lane = threadIdx.x & 31, wid = threadIdx.x >> 5;
    const int Rm = (wid & 3) * 32, Cn = (wid >> 2) * 64;
    const int gp = lane >> 2, qd = lane & 3;

    #pragma unroll
    for (int ni = 0; ni < 8; ni++) {
        const int n0 = nt * 128 + Cn + ni * 8 + qd * 2;
        const float2 bb = *(const float2*)&bias[n0];
        #pragma unroll
        for (int mi = 0; mi < 2; mi++) {
            const int m = r0 + Rm + mi * 16 + gp;
            *(float2*)(out + (size_t)m * DMODEL + n0) =
                make_float2(acc[mi][ni][0] + bb.x, acc[mi][ni][1] + bb.y);
            *(float2*)(out + (size_t)(m + 8) * DMODEL + n0) =
                make_float2(acc[mi][ni][2] + bb.x, acc[mi][ni][3] + bb.y);
        }
    }
}

// ================= tensor-core flash attention (ldmatrix + term-major) =================
#define FSTRIDE 72
#define FTILE   (64 * FSTRIDE * 2)
#define FL_Q    0
#define FL_ST   (2 * FTILE)
#define FL_STG  (4 * FTILE)
#define FLASH2_SMEM (FL_ST + 2 * FL_STG)  // 92160

__global__ __launch_bounds__(256, 2)
void flash_mma(const __nv_bfloat16* __restrict__ Qh_g, const __nv_bfloat16* __restrict__ Ql_g,
               const __nv_bfloat16* __restrict__ Kh_g, const __nv_bfloat16* __restrict__ Kl_g,
               const __nv_bfloat16* __restrict__ Vth_g, const __nv_bfloat16* __restrict__ Vtl_g,
               __nv_bfloat16* __restrict__ Ohi, __nv_bfloat16* __restrict__ Olo)
{
    extern __shared__ __align__(16) char smem[];
    const int tid = threadIdx.x, lane = tid & 31, wid = tid >> 5;
    const int qw = wid & 3, kw = wid >> 2;
    const int gp = lane >> 2, qd = lane & 3;
    const int lr = lane & 7, sel = lane >> 3;
    const int aOff = ((sel & 1) * 8 + lr) * FSTRIDE + (sel & 2) * 4;
    const int bOff = ((sel >> 1) * 8 + lr) * FSTRIDE + (sel & 1) * 8;
    const int h = blockIdx.y, q0 = blockIdx.x * 64;
    const unsigned sb = smem_u32(smem);

    const size_t hb  = (size_t)h * S_TOT * DH;
    const size_t hbT = (size_t)h * DH * S_TOT;

    // stage Q once
    {
        const __nv_bfloat16* src[2] = {Qh_g + hb + (size_t)q0 * DH, Ql_g + hb + (size_t)q0 * DH};
        #pragma unroll
        for (int t = 0; t < 2; t++) {
            const unsigned db = sb + FL_Q + t * FTILE;
            for (int i = tid; i < 512; i += 256) {
                const int row = i >> 3, cg = i & 7;
                cp16(db + (row * FSTRIDE + cg * 8) * 2, src[t] + (size_t)row * DH + cg * 8);
            }
        }
        asm volatile("cp.async.commit_group;" ::: "memory");
    }

    auto issueKV = [&](int kt, int stage) {
        const __nv_bfloat16* src[4] = {
            Kh_g  + hb  + (size_t)(kt * 64) * DH,
            Kl_g  + hb  + (size_t)(kt * 64) * DH,
            Vth_g + hbT + kt * 64,
            Vtl_g + hbT + kt * 64};
        #pragma unroll
        for (int t = 0; t < 4; t++) {
            const unsigned db = sb + FL_ST + stage * FL_STG + t * FTILE;
            const size_t rs = (t < 2) ? (size_t)DH : (size_t)S_TOT;
            for (int i = tid; i < 512; i += 256) {
                const int row = i >> 3, cg = i & 7;
                cp16(db + (row * FSTRIDE + cg * 8) * 2, src[t] + (size_t)row * rs + cg * 8);
            }
        }
        asm volatile("cp.async.commit_group;" ::: "memory");
    };

    issueKV(0, 0);

    float oacc[8][4];
    #pragma unroll
    for (int ni = 0; ni < 8; ni++)
        #pragma unroll
        for (int j = 0; j < 4; j++) oacc[ni][j] = 0.0f;
    float lpart[2] = {0.0f, 0.0f};

    for (int kt = 0; kt < S_TOT / 64; kt++) {
        asm volatile("cp.async.wait_group 0;" ::: "memory");
        __syncthreads();
        if (kt + 1 < S_TOT / 64) issueKV(kt + 1, (kt + 1) & 1);

        const unsigned uK = sb + FL_ST + (kt & 1) * FL_STG;
        const unsigned uV = uK + 2 * FTILE;

        // ---- S = Q K^T (3-term, term-major: dep distance 4) ----
        float sacc[4][4];
        #pragma unroll
        for (int ni = 0; ni < 4; ni++)
            #pragma unroll
            for (int j = 0; j < 4; j++) sacc[ni][j] = 0.0f;

        #pragma unroll
        for (int k0 = 0; k0 < 64; k0 += 16) {
            uint32_t ah[4], al[4];
            const unsigned ao = sb + FL_Q + 2u * (qw * 16 * FSTRIDE + k0 + aOff);
            ldsm4(ah, ao);
            ldsm4(al, ao + FTILE);
            uint32_t bh[2][4], bl[2][4];
            #pragma unroll
            for (int np = 0; np < 2; np++) {
                const unsigned bo = uK + 2u * ((kw * 32 + np * 16) * FSTRIDE + k0 + bOff);
                ldsm4(bh[np], bo);
                ldsm4(bl[np], bo + FTILE);
            }
            #pragma unroll
            for (int np = 0; np < 2; np++) {
                mma16816(sacc[2 * np],     ah, bh[np][0], bh[np][1]);
                mma16816(sacc[2 * np + 1], ah, bh[np][2], bh[np][3]);
            }
            #pragma unroll
            for (int np = 0; np < 2; np++) {
                mma16816(sacc[2 * np],     ah, bl[np][0], bl[np][1]);
                mma16816(sacc[2 * np + 1], ah, bl[np][2], bl[np][3]);
            }
            #pragma unroll
            for (int np = 0; np < 2; np++) {
                mma16816(sacc[2 * np],     al, bh[np][0], bh[np][1]);
                mma16816(sacc[2 * np + 1], al, bh[np][2], bh[np][3]);
            }
        }

        // ---- exp (no max: |s|<=8), build P hi/lo A-fragments in registers ----
        uint32_t pA[2][4], plA[2][4];
        #pragma unroll
        for (int ni = 0; ni < 4; ni++) {
            const float p0 = __expf(sacc[ni][0]), p1 = __expf(sacc[ni][1]);
            const float p2 = __expf(sacc[ni][2]), p3 = __expf(sacc[ni][3]);
            lpart[0] += p0 + p1;
            lpart[1] += p2 + p3;
            const int kc = ni >> 1, half = (ni & 1) << 1;
            pA[kc][half]      = bfpair(p0, p1);
            pA[kc][half + 1]  = bfpair(p2, p3);
            plA[kc][half]     = bfpair(p0 - bfround(p0), p1 - bfround(p1));
            plA[kc][half + 1] = bfpair(p2 - bfround(p2), p3 - bfround(p3));
        }

        // ---- O += P V (3-term, term-major over np-pairs: dep distance 4) ----
        #pragma unroll
        for (int kc = 0; kc < 2; kc++) {
            const int kk = kw * 32 + kc * 16;
            #pragma unroll
            for (int npp = 0; npp < 4; npp += 2) {
                uint32_t bh[2][4], bl[2][4];
                #pragma unroll
                for (int q = 0; q < 2; q++) {
                    const unsigned bo = uV + 2u * ((npp + q) * 16 * FSTRIDE + kk + bOff);
                    ldsm4(bh[q], bo);
                    ldsm4(bl[q], bo + FTILE);
                }
                #pragma unroll
                for (int q = 0; q < 2; q++) {
                    mma16816(oacc[2 * (npp + q)],     pA[kc], bh[q][0], bh[q][1]);
                    mma16816(oacc[2 * (npp + q) + 1], pA[kc], bh[q][2], bh[q][3]);
                }
                #pragma unroll
                for (int q = 0; q < 2; q++) {
                    mma16816(oacc[2 * (npp + q)],     pA[kc], bl[q][0], bl[q][1]);
                    mma16816(oacc[2 * (npp + q) + 1], pA[kc], bl[q][2], bl[q][3]);
                }
                #pragma unroll
                for (int q = 0; q < 2; q++) {
                    mma16816(oacc[2 * (npp + q)],     plA[kc], bh[q][0], bh[q][1]);
                    mma16816(oacc[2 * (npp + q) + 1], plA[kc], bh[q][2], bh[q][3]);
                }
            }
        }
    }

    // ---- final reduction across k-warps + 1/l scaling, bf16 hi/lo output ----
    __syncthreads();
    float* ored = (float*)(smem + FL_ST);
    float* lred = (float*)(smem + FL_ST + 4 * 16 * 68 * 4);

    #pragma unroll
    for (int off = 1; off < 4; off <<= 1) {
        lpart[0] += __shfl_xor_sync(0xffffffffu, lpart[0], off);
        lpart[1] += __shfl_xor_sync(0xffffffffu, lpart[1], off);
    }
    if (qd == 0) {
        lred[(kw * 4 + qw) * 16 + gp]     = lpart[0];
        lred[(kw * 4 + qw) * 16 + gp + 8] = lpart[1];
    }
    if (kw == 1) {
        #pragma unroll
        for (int ni = 0; ni < 8; ni++) {
            *(float2*)&ored[(qw * 16 + gp) * 68 + ni * 8 + 2 * qd] =
                make_float2(oacc[ni][0], oacc[ni][1]);
            *(float2*)&ored[(qw * 16 + gp + 8) * 68 + ni * 8 + 2 * qd] =
                make_float2(oacc[ni][2], oacc[ni][3]);
        }
    }
    __syncthreads();
    if (kw == 0) {
        const float inv0 = 1.0f / (lred[qw * 16 + gp]     + lred[(4 + qw) * 16 + gp]);
        const float inv1 = 1.0f / (lred[qw * 16 + gp + 8] + lred[(4 + qw) * 16 + gp + 8]);
        #pragma unroll
        for (int ni = 0; ni < 8; ni++) {
            const float2 a = *(const float2*)&ored[(qw * 16 + gp) * 68 + ni * 8 + 2 * qd];
            const float2 b = *(const float2*)&ored[(qw * 16 + gp + 8) * 68 + ni * 8 + 2 * qd];
            const int col = h * 64 + ni * 8 + 2 * qd;
            const float v0 = (oacc[ni][0] + a.x) * inv0, v1 = (oacc[ni][1] + a.y) * inv0;
            const float v2 = (oacc[ni][2] + b.x) * inv1, v3 = (oacc[ni][3] + b.y) * inv1;
            const size_t o0 = (size_t)(q0 + qw * 16 + gp) * DMODEL + col;
            const size_t o1 = (size_t)(q0 + qw * 16 + gp + 8) * DMODEL + col;
            const __nv_bfloat16 h0 = __float2bfloat16(v0), h1 = __float2bfloat16(v1);
            const __nv_bfloat16 h2 = __float2bfloat16(v2), h3 = __float2bfloat16(v3);
            *(__nv_bfloat162*)&Ohi[o0] = __nv_bfloat162{h0, h1};
            *(__nv_bfloat162*)&Ohi[o1] = __nv_bfloat162{h2, h3};
            *(__nv_bfloat162*)&Olo[o0] = __nv_bfloat162{
                __float2bfloat16(v0 - __bfloat162float(h0)),
                __float2bfloat16(v1 - __bfloat162float(h1))};
            *(__nv_bfloat162*)&Olo[o1] = __nv_bfloat162{
                __float2bfloat16(v2 - __bfloat162float(h2)),
                __float2bfloat16(v3 - __bfloat162float(h3))};
        }
    }
}

// ---------------- launch ----------------
extern "C" void kernel_launch(void* const* d_in, const int* in_sizes, int n_in,
                              void* d_out, int out_size)
{
    const float* hid  = (const float*)d_in[0];
    const float* enc  = (const float*)d_in[1];
    const float* rcos = (const float*)d_in[2];
    const float* rsin = (const float*)d_in[3];
    const float* Wq  = (const float*)d_in[4];  const float* bq  = (const float*)d_in[5];
    const float* Wk  = (const float*)d_in[6];  const float* bk  = (const float*)d_in[7];
    const float* Wv  = (const float*)d_in[8];  const float* bv  = (const float*)d_in[9];
    const float* Waq = (const float*)d_in[10]; const float* baq = (const float*)d_in[11];
    const float* Wak = (const float*)d_in[12]; const float* bak = (const float*)d_in[13];
    const float* Wav = (const float*)d_in[14]; const float* bav = (const float*)d_in[15];
    const float* Wo  = (const float*)d_in[16]; const float* bo  = (const float*)d_in[17];
    const float* Wao = (const float*)d_in[18]; const float* bao = (const float*)d_in[19];
    const float* gq  = (const float*)d_in[20]; const float* gk  = (const float*)d_in[21];
    const float* gaq = (const float*)d_in[22]; const float* gak = (const float*)d_in[23];
    float* out = (float*)d_out;

    float *Qp, *Kp, *Vp;
    cudaGetSymbolAddress((void**)&Qp, g_Q);
    cudaGetSymbolAddress((void**)&Kp, g_K);
    cudaGetSymbolAddress((void**)&Vp, g_V);
    __nv_bfloat16 *WhiP, *WloP, *XhiP, *XloP, *OhiP, *OloP;
    __nv_bfloat16 *QhP, *QlP, *KhP, *KlP, *VthP, *VtlP;
    cudaGetSymbolAddress((void**)&WhiP, g_Whi);
    cudaGetSymbolAddress((void**)&WloP, g_Wlo);
    cudaGetSymbolAddress((void**)&XhiP, g_Xhi);
    cudaGetSymbolAddress((void**)&XloP, g_Xlo);
    cudaGetSymbolAddress((void**)&OhiP, g_Ohi);
    cudaGetSymbolAddress((void**)&OloP, g_Olo);
    cudaGetSymbolAddress((void**)&QhP, g_Qhi);
    cudaGetSymbolAddress((void**)&QlP, g_Qlo);
    cudaGetSymbolAddress((void**)&KhP, g_Khi);
    cudaGetSymbolAddress((void**)&KlP, g_Klo);
    cudaGetSymbolAddress((void**)&VthP, g_Vthi);
    cudaGetSymbolAddress((void**)&VtlP, g_Vtlo);

    // splits: weights (one launch) + activations
    splitW<<<dim3((WSZ / 4 + 255) / 256, 8), 256>>>(Wq, Wk, Wv, Waq, Wak, Wav, Wo, Wao, WhiP, WloP);
    split4<<<(S_TXT * DMODEL / 4 + 255) / 256, 256>>>(enc, XhiP, XloP, S_TXT * DMODEL / 4);
    split4<<<(S_IMG * DMODEL / 4 + 255) / 256, 256>>>(hid, XhiP + (size_t)S_TXT * DMODEL,
                                                      XloP + (size_t)S_TXT * DMODEL, S_IMG * DMODEL / 4);

    // QKV projections (tensor cores) -> fp32 [h][s][d]
    cudaFuncSetAttribute(qkv_mma, cudaFuncAttributeMaxDynamicSharedMemorySize, GEMM_SMEM);
    qkv_mma<<<dim3(36, 20), 256, GEMM_SMEM>>>(XhiP, XloP, WhiP, WloP,
                                              bq, bk, bv, baq, bak, bav, Qp, Kp, Vp);

    // RMS norm + gain + RoPE, fused bf16 hi/lo split (Q scaled by 0.125)
    rmsrope_split<<<NH * S_TOT / 4, 128>>>(Qp, gaq, gq, rcos, rsin, 0.125f, QhP, QlP);
    rmsrope_split<<<NH * S_TOT / 4, 128>>>(Kp, gak, gk, rcos, rsin, 1.0f,   KhP, KlP);

    // V transpose+split
    vtsplit<<<dim3(S_TOT / 32, DH / 32, NH), dim3(32, 8)>>>(Vp, VthP, VtlP);

    // tensor-core flash attention -> bf16 hi/lo O[s][h*64+d]
    cudaFuncSetAttribute(flash_mma, cudaFuncAttributeMaxDynamicSharedMemorySize, FLASH2_SMEM);
    flash_mma<<<dim3(S_TOT / 64, NH), 256, FLASH2_SMEM>>>(QhP, QlP, KhP, KlP, VthP, VtlP, OhiP, OloP);

    // output projections (tensor cores)
    cudaFuncSetAttribute(out_mma, cudaFuncAttributeMaxDynamicSharedMemorySize, GEMM_SMEM);
    out_mma<<<dim3(12, 20), 256, GEMM_SMEM>>>(OhiP, OloP, WhiP, WloP, bo, bao, out);
}

// round 16
// speedup vs baseline: 1.0172x; 1.0172x over previous
#include <cuda_runtime.h>
#include <cuda_bf16.h>
#include <cstddef>
#include <cstdint>

#define S_IMG  2048
#define S_TXT  512
#define S_TOT  2560
#define DMODEL 1536
#define NH     24
#define DH     64

typedef unsigned long long ull;

// ---------------- scratch (no allocations allowed) ----------------
#define WSZ (DMODEL * DMODEL)
#define QKVN (NH * S_TOT * DH)
__device__ __align__(16) __nv_bfloat16 g_Whi[8 * WSZ];
__device__ __align__(16) __nv_bfloat16 g_Wlo[8 * WSZ];
__device__ __align__(16) __nv_bfloat16 g_Xhi[S_TOT * DMODEL];
__device__ __align__(16) __nv_bfloat16 g_Xlo[S_TOT * DMODEL];
__device__ __align__(16) __nv_bfloat16 g_Ohi[S_TOT * DMODEL]; // [s][h*64+d]
__device__ __align__(16) __nv_bfloat16 g_Olo[S_TOT * DMODEL];
__device__ __align__(16) __nv_bfloat16 g_Qhi[QKVN], g_Qlo[QKVN];   // [h][s][d], x0.125
__device__ __align__(16) __nv_bfloat16 g_Khi[QKVN], g_Klo[QKVN];   // [h][s][d]
__device__ __align__(16) __nv_bfloat16 g_Vthi[QKVN], g_Vtlo[QKVN]; // [h][d][s]

// ---------------- helpers ----------------
__device__ __forceinline__ unsigned smem_u32(const void* p) {
    unsigned a;
    asm("{ .reg .u64 t; cvta.to.shared.u64 t, %1; cvt.u32.u64 %0, t; }" : "=r"(a) : "l"(p));
    return a;
}
__device__ __forceinline__ void cp16(unsigned dst, const void* src) {
    asm volatile("cp.async.cg.shared.global [%0], [%1], 16;" :: "r"(dst), "l"(src) : "memory");
}
__device__ __forceinline__ void ldsm4(uint32_t* r, unsigned a) {
    asm volatile("ldmatrix.sync.aligned.m8n8.x4.shared.b16 {%0,%1,%2,%3}, [%4];"
        : "=r"(r[0]), "=r"(r[1]), "=r"(r[2]), "=r"(r[3]) : "r"(a));
}
__device__ __forceinline__ void mma16816(float* c, const uint32_t* a, uint32_t b0, uint32_t b1) {
    asm("mma.sync.aligned.m16n8k16.row.col.f32.bf16.bf16.f32 "
        "{%0,%1,%2,%3}, {%4,%5,%6,%7}, {%8,%9}, {%0,%1,%2,%3};"
        : "+f"(c[0]), "+f"(c[1]), "+f"(c[2]), "+f"(c[3])
        : "r"(a[0]), "r"(a[1]), "r"(a[2]), "r"(a[3]), "r"(b0), "r"(b1));
}
__device__ __forceinline__ uint32_t bfpair(float lo, float hi) {   // reg.lo=lo, reg.hi=hi
    uint32_t r; asm("cvt.rn.bf16x2.f32 %0, %1, %2;" : "=r"(r) : "f"(hi), "f"(lo)); return r;
}
__device__ __forceinline__ float bfround(float x) {
    return __bfloat162float(__float2bfloat16(x));
}

// ---------------- splits ----------------
__global__ void split4(const float* __restrict__ src, __nv_bfloat16* __restrict__ hi,
                       __nv_bfloat16* __restrict__ lo, int n4)
{
    int i = blockIdx.x * 256 + threadIdx.x;
    if (i < n4) {
        float4 v = ((const float4*)src)[i];
        __nv_bfloat162 h0{__float2bfloat16(v.x), __float2bfloat16(v.y)};
        __nv_bfloat162 h1{__float2bfloat16(v.z), __float2bfloat16(v.w)};
        ((__nv_bfloat162*)hi)[2 * i]     = h0;
        ((__nv_bfloat162*)hi)[2 * i + 1] = h1;
        __nv_bfloat162 l0{__float2bfloat16(v.x - __bfloat162float(h0.x)),
                          __float2bfloat16(v.y - __bfloat162float(h0.y))};
        __nv_bfloat162 l1{__float2bfloat16(v.z - __bfloat162float(h1.x)),
                          __float2bfloat16(v.w - __bfloat162float(h1.y))};
        ((__nv_bfloat162*)lo)[2 * i]     = l0;
        ((__nv_bfloat162*)lo)[2 * i + 1] = l1;
    }
}

__global__ void splitW(const float* w0, const float* w1, const float* w2, const float* w3,
                       const float* w4, const float* w5, const float* w6, const float* w7,
                       __nv_bfloat16* __restrict__ hi, __nv_bfloat16* __restrict__ lo)
{
    const float* ws[8] = {w0, w1, w2, w3, w4, w5, w6, w7};
    const int wsel = blockIdx.y;
    const float* src = ws[wsel];
    int i = blockIdx.x * 256 + threadIdx.x;
    if (i < WSZ / 4) {
        float4 v = ((const float4*)src)[i];
        const size_t o2 = (size_t)wsel * (WSZ / 2) + 2 * i;
        __nv_bfloat162 h0{__float2bfloat16(v.x), __float2bfloat16(v.y)};
        __nv_bfloat162 h1{__float2bfloat16(v.z), __float2bfloat16(v.w)};
        ((__nv_bfloat162*)hi)[o2]     = h0;
        ((__nv_bfloat162*)hi)[o2 + 1] = h1;
        __nv_bfloat162 l0{__float2bfloat16(v.x - __bfloat162float(h0.x)),
                          __float2bfloat16(v.y - __bfloat162float(h0.y))};
        __nv_bfloat162 l1{__float2bfloat16(v.z - __bfloat162float(h1.x)),
                          __float2bfloat16(v.w - __bfloat162float(h1.y))};
        ((__nv_bfloat162*)lo)[o2]     = l0;
        ((__nv_bfloat162*)lo)[o2 + 1] = l1;
    }
}

// ================= warp-MMA bf16 GEMM core (validated) =================
#define GBK      32
#define GSTRIDE  40
#define GBUF     (128 * GSTRIDE * 2)
#define GSTAGE   (4 * GBUF)
#define GEMM_SMEM (2 * GSTAGE)

__device__ void mma_core(const __nv_bfloat16* __restrict__ Ah, const __nv_bfloat16* __restrict__ Al,
                         const __nv_bfloat16* __restrict__ Wh, const __nv_bfloat16* __restrict__ Wl,
                         char* smem, float acc[2][8][4])
{
    const int tid  = threadIdx.x;
    const int lane = tid & 31;
    const int wid  = tid >> 5;
    const int Rm   = (wid & 3) * 32;
    const int Cn   = (wid >> 2) * 64;
    const int lr   = lane & 7, sel = lane >> 3;
    const int aOff = ((sel & 1) * 8 + lr) * GSTRIDE + (sel & 2) * 4;
    const int bOff = ((sel >> 1) * 8 + lr) * GSTRIDE + (sel & 1) * 8;

    const unsigned sb = smem_u32(smem);
    const __nv_bfloat16* gsrc[4] = {Ah, Al, Wh, Wl};

    auto issue = [&](int c, int stage) {
        #pragma unroll
        for (int t4 = 0; t4 < 4; t4++) {
            const __nv_bfloat16* s = gsrc[t4] + c * GBK;
            const unsigned dbase = sb + stage * GSTAGE + t4 * GBUF;
            #pragma unroll
            for (int i = 0; i < 2; i++) {
                const int idx = tid + i * 256;
                const int row = idx >> 2, cg = idx & 3;
                cp16(dbase + (row * GSTRIDE + cg * 8) * 2,
                     s + (size_t)row * DMODEL + cg * 8);
            }
        }
        asm volatile("cp.async.commit_group;" ::: "memory");
    };

    #pragma unroll
    for (int mi = 0; mi < 2; mi++)
        #pragma unroll
        for (int ni = 0; ni < 8; ni++)
            #pragma unroll
            for (int j = 0; j < 4; j++) acc[mi][ni][j] = 0.0f;

    issue(0, 0);

    for (int c = 0; c < DMODEL / GBK; c++) {
        asm volatile("cp.async.wait_group 0;" ::: "memory");
        __syncthreads();
        if (c + 1 < DMODEL / GBK) issue(c + 1, (c + 1) & 1);

        const unsigned uSt = sb + (c & 1) * GSTAGE;

        #pragma unroll
        for (int k0 = 0; k0 < GBK; k0 += 16) {
            uint32_t ah[2][4], al[2][4];
            #pragma unroll
            for (int mi = 0; mi < 2; mi++) {
                const unsigned ao = uSt + 2u * ((Rm + mi * 16) * GSTRIDE + k0 + aOff);
                ldsm4(ah[mi], ao);
                ldsm4(al[mi], ao + GBUF);
            }
            #pragma unroll
            for (int npp = 0; npp < 4; npp += 2) {
                uint32_t bh[2][4], bl[2][4];
                #pragma unroll
                for (int q = 0; q < 2; q++) {
                    const unsigned bo = uSt + 2 * GBUF +
                        2u * ((Cn + (npp + q) * 16) * GSTRIDE + k0 + bOff);
                    ldsm4(bh[q], bo);
                    ldsm4(bl[q], bo + GBUF);
                }
                #pragma unroll
                for (int q = 0; q < 2; q++)
                    #pragma unroll
                    for (int mi = 0; mi < 2; mi++) {
                        mma16816(acc[mi][2 * (npp + q)],     ah[mi], bh[q][0], bh[q][1]);
                        mma16816(acc[mi][2 * (npp + q) + 1], ah[mi], bh[q][2], bh[q][3]);
                    }
                #pragma unroll
                for (int q = 0; q < 2; q++)
                    #pragma unroll
                    for (int mi = 0; mi < 2; mi++) {
                        mma16816(acc[mi][2 * (npp + q)],     ah[mi], bl[q][0], bl[q][1]);
                        mma16816(acc[mi][2 * (npp + q) + 1], ah[mi], bl[q][2], bl[q][3]);
                    }
                #pragma unroll
                for (int q = 0; q < 2; q++)
                    #pragma unroll
                    for (int mi = 0; mi < 2; mi++) {
                        mma16816(acc[mi][2 * (npp + q)],     al[mi], bh[q][0], bh[q][1]);
                        mma16816(acc[mi][2 * (npp + q) + 1], al[mi], bh[q][2], bh[q][3]);
                    }
            }
        }
    }
}

// ---------------- QKV projection + fused RMS/RoPE/split epilogues ----------------
// grid (36, 20). Each warp's 64 n-cols = one head's full d-range, so the row
// sum-of-squares for RMS lives in one quad (2 shfl_xor), and RoPE pairs
// (2i, 2i+1) are thread-local.
__global__ __launch_bounds__(256, 2)
void qkv_mma(const __nv_bfloat16* __restrict__ Xhi, const __nv_bfloat16* __restrict__ Xlo,
             const __nv_bfloat16* __restrict__ Whi8, const __nv_bfloat16* __restrict__ Wlo8,
             const float* __restrict__ bq, const float* __restrict__ bk, const float* __restrict__ bv,
             const float* __restrict__ baq, const float* __restrict__ bak, const float* __restrict__ bav,
             const float* __restrict__ gq, const float* __restrict__ gk,
             const float* __restrict__ gaq, const float* __restrict__ gak,
             const float* __restrict__ rcos, const float* __restrict__ rsin,
             __nv_bfloat16* __restrict__ Qhi, __nv_bfloat16* __restrict__ Qlo,
             __nv_bfloat16* __restrict__ Khi, __nv_bfloat16* __restrict__ Klo,
             __nv_bfloat16* __restrict__ Vthi, __nv_bfloat16* __restrict__ Vtlo)
{
    extern __shared__ __align__(16) char smem[];
    const int bx = blockIdx.x, mt = blockIdx.y;
    const int proj = bx / 12;
    const int n0b  = (bx % 12) * 128;
    const bool txt = (mt < 4);
    const int widx = (txt ? 3 : 0) + proj;

    const __nv_bfloat16* Ah = Xhi + (size_t)mt * 128 * DMODEL;
    const __nv_bfloat16* Al = Xlo + (size_t)mt * 128 * DMODEL;
    const __nv_bfloat16* Wh = Whi8 + (size_t)widx * WSZ + (size_t)n0b * DMODEL;
    const __nv_bfloat16* Wl = Wlo8 + (size_t)widx * WSZ + (size_t)n0b * DMODEL;
    const float* bias = txt ? (proj == 0 ? baq : proj == 1 ? bak : bav)
                            : (proj == 0 ? bq  : proj == 1 ? bk  : bv);

    float acc[2][8][4];
    mma_core(Ah, Al, Wh, Wl, smem, acc);

    const int lane = threadIdx.x & 31, wid = threadIdx.x >> 5;
    const int Rm = (wid & 3) * 32, Cn = (wid >> 2) * 64;
    const int gp = lane >> 2, qd = lane & 3;
    const int headN = n0b + Cn;       // multiple of 64
    const int hh = headN >> 6;

    // bias first (reference order: proj + bias, then RMS)
    #pragma unroll
    for (int ni = 0; ni < 8; ni++) {
        const float2 bb = *(const float2*)&bias[headN + ni * 8 + qd * 2];
        #pragma unroll
        for (int mi = 0; mi < 2; mi++) {
            acc[mi][ni][0] += bb.x; acc[mi][ni][1] += bb.y;
            acc[mi][ni][2] += bb.x; acc[mi][ni][3] += bb.y;
        }
    }

    if (proj < 2) {
        const float* g = txt ? (proj == 0 ? gaq : gak) : (proj == 0 ? gq : gk);
        const float scale = (proj == 0) ? 0.125f : 1.0f;
        __nv_bfloat16* oh = (proj == 0) ? Qhi : Khi;
        __nv_bfloat16* ol = (proj == 0) ? Qlo : Klo;
        float gv[8][2];
        #pragma unroll
        for (int ni = 0; ni < 8; ni++) {
            gv[ni][0] = g[ni * 8 + qd * 2];
            gv[ni][1] = g[ni * 8 + qd * 2 + 1];
        }
        #pragma unroll
        for (int mi = 0; mi < 2; mi++)
            #pragma unroll
            for (int half = 0; half < 2; half++) {
                const int srow = mt * 128 + Rm + mi * 16 + gp + 8 * half;
                float ss = 0.0f;
                #pragma unroll
                for (int ni = 0; ni < 8; ni++) {
                    const float a0 = acc[mi][ni][2 * half], a1 = acc[mi][ni][2 * half + 1];
                    ss += a0 * a0 + a1 * a1;
                }
                ss += __shfl_xor_sync(0xffffffffu, ss, 1);   // reduce over the quad (qd)
                ss += __shfl_xor_sync(0xffffffffu, ss, 2);
                const float rr = rsqrtf(ss * (1.0f / 64.0f) + 1e-6f);
                #pragma unroll
                for (int ni = 0; ni < 8; ni++) {
                    const int d = ni * 8 + qd * 2;
                    const float y0 = acc[mi][ni][2 * half]     * rr * gv[ni][0];
                    const float y1 = acc[mi][ni][2 * half + 1] * rr * gv[ni][1];
                    const float c  = rcos[srow * 64 + d];    // pairwise-repeated
                    const float sn = rsin[srow * 64 + d];
                    const float o0 = (y0 * c - y1 * sn) * scale;
                    const float o1 = (y1 * c + y0 * sn) * scale;
                    const __nv_bfloat16 h0 = __float2bfloat16(o0);
                    const __nv_bfloat16 h1 = __float2bfloat16(o1);
                    const size_t off = (((size_t)hh * S_TOT + srow) << 6) + d;
                    *(__nv_bfloat162*)&oh[off] = __nv_bfloat162{h0, h1};
                    *(__nv_bfloat162*)&ol[off] = __nv_bfloat162{
                        __float2bfloat16(o0 - __bfloat162float(h0)),
                        __float2bfloat16(o1 - __bfloat162float(h1))};
                }
            }
    } else {
        // V: transposed hi/lo write, Vt[h][d][s]
        #pragma unroll
        for (int mi = 0; mi < 2; mi++)
            #pragma unroll
            for (int half = 0; half < 2; half++) {
                const int srow = mt * 128 + Rm + mi * 16 + gp + 8 * half;
                #pragma unroll
                for (int ni = 0; ni < 8; ni++) {
                    const int d = ni * 8 + qd * 2;
                    const float v0 = acc[mi][ni][2 * half], v1 = acc[mi][ni][2 * half + 1];
                    const __nv_bfloat16 h0 = __float2bfloat16(v0);
                    const __nv_bfloat16 h1 = __float2bfloat16(v1);
                    const size_t o0 = ((size_t)hh * DH + d) * S_TOT + srow;
                    Vthi[o0]         = h0;
                    Vthi[o0 + S_TOT] = h1;
                    Vtlo[o0]         = __float2bfloat16(v0 - __bfloat162float(h0));
                    Vtlo[o0 + S_TOT] = __float2bfloat16(v1 - __bfloat162float(h1));
                }
            }
    }
}

__global__ __launch_bounds__(256, 2)
void out_mma(const __nv_bfloat16* __restrict__ Ohi, const __nv_bfloat16* __restrict__ Olo,
             const __nv_bfloat16* __restrict__ Whi8, const __nv_bfloat16* __restrict__ Wlo8,
             const float* __restrict__ bo, const float* __restrict__ bao,
             float* __restrict__ out)
{
    extern __shared__ __align__(16) char smem[];
    const int nt = blockIdx.x, mt = blockIdx.y;
    const int r0 = mt * 128;
    const bool img = (r0 < S_IMG);
    const size_t arow = img ? (size_t)(S_TXT + r0) : (size_t)(r0 - S_IMG);
    const int widx = img ? 6 : 7;

    const __nv_bfloat16* Ah = Ohi + arow * DMODEL;
    const __nv_bfloat16* Al = Olo + arow * DMODEL;
    const __nv_bfloat16* Wh = Whi8 + (size_t)widx * WSZ + (size_t)nt * 128 * DMODEL;
    const __nv_bfloat16* Wl = Wlo8 + (size_t)widx * WSZ + (size_t)nt * 128 * DMODEL;
    const float* bias = img ? bo : bao;

    float acc[2][8][4];
    mma_core(Ah, Al, Wh, Wl, smem, acc);

    const int lane = threadIdx.x & 31, wid = threadIdx.x >> 5;
    const int Rm = (wid & 3) * 32, Cn = (wid >> 2) * 64;
    const int gp = lane >> 2, qd = lane & 3;

    #pragma unroll
    for (int ni = 0; ni < 8; ni++) {
        const int n0 = nt * 128 + Cn + ni * 8 + qd * 2;
        const float2 bb = *(const float2*)&bias[n0];
        #pragma unroll
        for (int mi = 0; mi < 2; mi++) {
            const int m = r0 + Rm + mi * 16 + gp;
            *(float2*)(out + (size_t)m * DMODEL + n0) =
                make_float2(acc[mi][ni][0] + bb.x, acc[mi][ni][1] + bb.y);
            *(float2*)(out + (size_t)(m + 8) * DMODEL + n0) =
                make_float2(acc[mi][ni][2] + bb.x, acc[mi][ni][3] + bb.y);
        }
    }
}

// ================= tensor-core flash attention (validated) =================
#define FSTRIDE 72
#define FTILE   (64 * FSTRIDE * 2)
#define FL_Q    0
#define FL_ST   (2 * FTILE)
#define FL_STG  (4 * FTILE)
#define FLASH2_SMEM (FL_ST + 2 * FL_STG)  // 92160

__global__ __launch_bounds__(256, 2)
void flash_mma(const __nv_bfloat16* __restrict__ Qh_g, const __nv_bfloat16* __restrict__ Ql_g,
               const __nv_bfloat16* __restrict__ Kh_g, const __nv_bfloat16* __restrict__ Kl_g,
               const __nv_bfloat16* __restrict__ Vth_g, const __nv_bfloat16* __restrict__ Vtl_g,
               __nv_bfloat16* __restrict__ Ohi, __nv_bfloat16* __restrict__ Olo)
{
    extern __shared__ __align__(16) char smem[];
    const int tid = threadIdx.x, lane = tid & 31, wid = tid >> 5;
    const int qw = wid & 3, kw = wid >> 2;
    const int gp = lane >> 2, qd = lane & 3;
    const int lr = lane & 7, sel = lane >> 3;
    const int aOff = ((sel & 1) * 8 + lr) * FSTRIDE + (sel & 2) * 4;
    const int bOff = ((sel >> 1) * 8 + lr) * FSTRIDE + (sel & 1) * 8;
    const int h = blockIdx.y, q0 = blockIdx.x * 64;
    const unsigned sb = smem_u32(smem);

    const size_t hb  = (size_t)h * S_TOT * DH;
    const size_t hbT = (size_t)h * DH * S_TOT;

    // stage Q once
    {
        const __nv_bfloat16* src[2] = {Qh_g + hb + (size_t)q0 * DH, Ql_g + hb + (size_t)q0 * DH};
        #pragma unroll
        for (int t = 0; t < 2; t++) {
            const unsigned db = sb + FL_Q + t * FTILE;
            for (int i = tid; i < 512; i += 256) {
                const int row = i >> 3, cg = i & 7;
                cp16(db + (row * FSTRIDE + cg * 8) * 2, src[t] + (size_t)row * DH + cg * 8);
            }
        }
        asm volatile("cp.async.commit_group;" ::: "memory");
    }

    auto issueKV = [&](int kt, int stage) {
        const __nv_bfloat16* src[4] = {
            Kh_g  + hb  + (size_t)(kt * 64) * DH,
            Kl_g  + hb  + (size_t)(kt * 64) * DH,
            Vth_g + hbT + kt * 64,
            Vtl_g + hbT + kt * 64};
        #pragma unroll
        for (int t = 0; t < 4; t++) {
            const unsigned db = sb + FL_ST + stage * FL_STG + t * FTILE;
            const size_t rs = (t < 2) ? (size_t)DH : (size_t)S_TOT;
            for (int i = tid; i < 512; i += 256) {
                const int row = i >> 3, cg = i & 7;
                cp16(db + (row * FSTRIDE + cg * 8) * 2, src[t] + (size_t)row * rs + cg * 8);
            }
        }
        asm volatile("cp.async.commit_group;" ::: "memory");
    };

    issueKV(0, 0);

    float oacc[8][4];
    #pragma unroll
    for (int ni = 0; ni < 8; ni++)
        #pragma unroll
        for (int j = 0; j < 4; j++) oacc[ni][j] = 0.0f;
    float lpart[2] = {0.0f, 0.0f};

    for (int kt = 0; kt < S_TOT / 64; kt++) {
        asm volatile("cp.async.wait_group 0;" ::: "memory");
        __syncthreads();
        if (kt + 1 < S_TOT / 64) issueKV(kt + 1, (kt + 1) & 1);

        const unsigned uK = sb + FL_ST + (kt & 1) * FL_STG;
        const unsigned uV = uK + 2 * FTILE;

        // ---- S = Q K^T (3-term) ----
        float sacc[4][4];
        #pragma unroll
        for (int ni = 0; ni < 4; ni++)
            #pragma unroll
            for (int j = 0; j < 4; j++) sacc[ni][j] = 0.0f;

        #pragma unroll
        for (int k0 = 0; k0 < 64; k0 += 16) {
            uint32_t ah[4], al[4];
            const unsigned ao = sb + FL_Q + 2u * (qw * 16 * FSTRIDE + k0 + aOff);
            ldsm4(ah, ao);
            ldsm4(al, ao + FTILE);
            uint32_t bh[2][4], bl[2][4];
            #pragma unroll
            for (int np = 0; np < 2; np++) {
                const unsigned bo = uK + 2u * ((kw * 32 + np * 16) * FSTRIDE + k0 + bOff);
                ldsm4(bh[np], bo);
                ldsm4(bl[np], bo + FTILE);
            }
            #pragma unroll
            for (int np = 0; np < 2; np++) {
                mma16816(sacc[2 * np],     ah, bh[np][0], bh[np][1]);
                mma16816(sacc[2 * np + 1], ah, bh[np][2], bh[np][3]);
            }
            #pragma unroll
            for (int np = 0; np < 2; np++) {
                mma16816(sacc[2 * np],     ah, bl[np][0], bl[np][1]);
                mma16816(sacc[2 * np + 1], ah, bl[np][2], bl[np][3]);
            }
            #pragma unroll
            for (int np = 0; np < 2; np++) {
                mma16816(sacc[2 * np],     al, bh[np][0], bh[np][1]);
                mma16816(sacc[2 * np + 1], al, bh[np][2], bh[np][3]);
            }
        }

        // ---- exp (no max: |s|<=8), build P hi/lo A-fragments ----
        uint32_t pA[2][4], plA[2][4];
        #pragma unroll
        for (int ni = 0; ni < 4; ni++) {
            const float p0 = __expf(sacc[ni][0]), p1 = __expf(sacc[ni][1]);
            const float p2 = __expf(sacc[ni][2]), p3 = __expf(sacc[ni][3]);
            lpart[0] += p0 + p1;
            lpart[1] += p2 + p3;
            const int kc = ni >> 1, half = (ni & 1) << 1;
            pA[kc][half]      = bfpair(p0, p1);
            pA[kc][half + 1]  = bfpair(p2, p3);
            plA[kc][half]     = bfpair(p0 - bfround(p0), p1 - bfround(p1));
            plA[kc][half + 1] = bfpair(p2 - bfround(p2), p3 - bfround(p3));
        }

        // ---- O += P V (3-term) ----
        #pragma unroll
        for (int kc = 0; kc < 2; kc++) {
            const int kk = kw * 32 + kc * 16;
            #pragma unroll
            for (int npp = 0; npp < 4; npp += 2) {
                uint32_t bh[2][4], bl[2][4];
                #pragma unroll
                for (int q = 0; q < 2; q++) {
                    const unsigned bo = uV + 2u * ((npp + q) * 16 * FSTRIDE + kk + bOff);
                    ldsm4(bh[q], bo);
                    ldsm4(bl[q], bo + FTILE);
                }
                #pragma unroll
                for (int q = 0; q < 2; q++) {
                    mma16816(oacc[2 * (npp + q)],     pA[kc], bh[q][0], bh[q][1]);
                    mma16816(oacc[2 * (npp + q) + 1], pA[kc], bh[q][2], bh[q][3]);
                }
                #pragma unroll
                for (int q = 0; q < 2; q++) {
                    mma16816(oacc[2 * (npp + q)],     pA[kc], bl[q][0], bl[q][1]);
                    mma16816(oacc[2 * (npp + q) + 1], pA[kc], bl[q][2], bl[q][3]);
                }
                #pragma unroll
                for (int q = 0; q < 2; q++) {
                    mma16816(oacc[2 * (npp + q)],     plA[kc], bh[q][0], bh[q][1]);
                    mma16816(oacc[2 * (npp + q) + 1], plA[kc], bh[q][2], bh[q][3]);
                }
            }
        }
    }

    // ---- final reduction across k-warps + 1/l scaling, bf16 hi/lo output ----
    __syncthreads();
    float* ored = (float*)(smem + FL_ST);
    float* lred = (float*)(smem + FL_ST + 4 * 16 * 68 * 4);

    #pragma unroll
    for (int off = 1; off < 4; off <<= 1) {
        lpart[0] += __shfl_xor_sync(0xffffffffu, lpart[0], off);
        lpart[1] += __shfl_xor_sync(0xffffffffu, lpart[1], off);
    }
    if (qd == 0) {
        lred[(kw * 4 + qw) * 16 + gp]     = lpart[0];
        lred[(kw * 4 + qw) * 16 + gp + 8] = lpart[1];
    }
    if (kw == 1) {
        #pragma unroll
        for (int ni = 0; ni < 8; ni++) {
            *(float2*)&ored[(qw * 16 + gp) * 68 + ni * 8 + 2 * qd] =
                make_float2(oacc[ni][0], oacc[ni][1]);
            *(float2*)&ored[(qw * 16 + gp + 8) * 68 + ni * 8 + 2 * qd] =
                make_float2(oacc[ni][2], oacc[ni][3]);
        }
    }
    __syncthreads();
    if (kw == 0) {
        const float inv0 = 1.0f / (lred[qw * 16 + gp]     + lred[(4 + qw) * 16 + gp]);
        const float inv1 = 1.0f / (lred[qw * 16 + gp + 8] + lred[(4 + qw) * 16 + gp + 8]);
        #pragma unroll
        for (int ni = 0; ni < 8; ni++) {
            const float2 a = *(const float2*)&ored[(qw * 16 + gp) * 68 + ni * 8 + 2 * qd];
            const float2 b = *(const float2*)&ored[(qw * 16 + gp + 8) * 68 + ni * 8 + 2 * qd];
            const int col = h * 64 + ni * 8 + 2 * qd;
            const float v0 = (oacc[ni][0] + a.x) * inv0, v1 = (oacc[ni][1] + a.y) * inv0;
            const float v2 = (oacc[ni][2] + b.x) * inv1, v3 = (oacc[ni][3] + b.y) * inv1;
            const size_t o0 = (size_t)(q0 + qw * 16 + gp) * DMODEL + col;
            const size_t o1 = (size_t)(q0 + qw * 16 + gp + 8) * DMODEL + col;
            const __nv_bfloat16 h0 = __float2bfloat16(v0), h1 = __float2bfloat16(v1);
            const __nv_bfloat16 h2 = __float2bfloat16(v2), h3 = __float2bfloat16(v3);
            *(__nv_bfloat162*)&Ohi[o0] = __nv_bfloat162{h0, h1};
            *(__nv_bfloat162*)&Ohi[o1] = __nv_bfloat162{h2, h3};
            *(__nv_bfloat162*)&Olo[o0] = __nv_bfloat162{
                __float2bfloat16(v0 - __bfloat162float(h0)),
                __float2bfloat16(v1 - __bfloat162float(h1))};
            *(__nv_bfloat162*)&Olo[o1] = __nv_bfloat162{
                __float2bfloat16(v2 - __bfloat162float(h2)),
                __float2bfloat16(v3 - __bfloat162float(h3))};
        }
    }
}

// ---------------- launch ----------------
extern "C" void kernel_launch(void* const* d_in, const int* in_sizes, int n_in,
                              void* d_out, int out_size)
{
    const float* hid  = (const float*)d_in[0];
    const float* enc  = (const float*)d_in[1];
    const float* rcos = (const float*)d_in[2];
    const float* rsin = (const float*)d_in[3];
    const float* Wq  = (const float*)d_in[4];  const float* bq  = (const float*)d_in[5];
    const float* Wk  = (const float*)d_in[6];  const float* bk  = (const float*)d_in[7];
    const float* Wv  = (const float*)d_in[8];  const float* bv  = (const float*)d_in[9];
    const float* Waq = (const float*)d_in[10]; const float* baq = (const float*)d_in[11];
    const float* Wak = (const float*)d_in[12]; const float* bak = (const float*)d_in[13];
    const float* Wav = (const float*)d_in[14]; const float* bav = (const float*)d_in[15];
    const float* Wo  = (const float*)d_in[16]; const float* bo  = (const float*)d_in[17];
    const float* Wao = (const float*)d_in[18]; const float* bao = (const float*)d_in[19];
    const float* gq  = (const float*)d_in[20]; const float* gk  = (const float*)d_in[21];
    const float* gaq = (const float*)d_in[22]; const float* gak = (const float*)d_in[23];
    float* out = (float*)d_out;

    __nv_bfloat16 *WhiP, *WloP, *XhiP, *XloP, *OhiP, *OloP;
    __nv_bfloat16 *QhP, *QlP, *KhP, *KlP, *VthP, *VtlP;
    cudaGetSymbolAddress((void**)&WhiP, g_Whi);
    cudaGetSymbolAddress((void**)&WloP, g_Wlo);
    cudaGetSymbolAddress((void**)&XhiP, g_Xhi);
    cudaGetSymbolAddress((void**)&XloP, g_Xlo);
    cudaGetSymbolAddress((void**)&OhiP, g_Ohi);
    cudaGetSymbolAddress((void**)&OloP, g_Olo);
    cudaGetSymbolAddress((void**)&QhP, g_Qhi);
    cudaGetSymbolAddress((void**)&QlP, g_Qlo);
    cudaGetSymbolAddress((void**)&KhP, g_Khi);
    cudaGetSymbolAddress((void**)&KlP, g_Klo);
    cudaGetSymbolAddress((void**)&VthP, g_Vthi);
    cudaGetSymbolAddress((void**)&VtlP, g_Vtlo);

    // splits: weights (one launch) + activations
    splitW<<<dim3((WSZ / 4 + 255) / 256, 8), 256>>>(Wq, Wk, Wv, Waq, Wak, Wav, Wo, Wao, WhiP, WloP);
    split4<<<(S_TXT * DMODEL / 4 + 255) / 256, 256>>>(enc, XhiP, XloP, S_TXT * DMODEL / 4);
    split4<<<(S_IMG * DMODEL / 4 + 255) / 256, 256>>>(hid, XhiP + (size_t)S_TXT * DMODEL,
                                                      XloP + (size_t)S_TXT * DMODEL, S_IMG * DMODEL / 4);

    // QKV projections + fused RMS/RoPE/split -> bf16 hi/lo Q,K [h][s][d], Vt [h][d][s]
    cudaFuncSetAttribute(qkv_mma, cudaFuncAttributeMaxDynamicSharedMemorySize, GEMM_SMEM);
    qkv_mma<<<dim3(36, 20), 256, GEMM_SMEM>>>(XhiP, XloP, WhiP, WloP,
                                              bq, bk, bv, baq, bak, bav,
                                              gq, gk, gaq, gak, rcos, rsin,
                                              QhP, QlP, KhP, KlP, VthP, VtlP);

    // tensor-core flash attention -> bf16 hi/lo O[s][h*64+d]
    cudaFuncSetAttribute(flash_mma, cudaFuncAttributeMaxDynamicSharedMemorySize, FLASH2_SMEM);
    flash_mma<<<dim3(S_TOT / 64, NH), 256, FLASH2_SMEM>>>(QhP, QlP, KhP, KlP, VthP, VtlP, OhiP, OloP);

    // output projections (tensor cores)
    cudaFuncSetAttribute(out_mma, cudaFuncAttributeMaxDynamicSharedMemorySize, GEMM_SMEM);
    out_mma<<<dim3(12, 20), 256, GEMM_SMEM>>>(OhiP, OloP, WhiP, WloP, bo, bao, out);
}